// round 15
// baseline (speedup 1.0000x reference)
#include <cuda_runtime.h>
#include <cuda_bf16.h>
#include <cstdint>

#define SEQ    1024
#define BSZ    2
#define DM     768
#define NH     12
#define DH     64
#define WIN    32
#define NW     (SEQ/WIN)
#define NABC   (5*NH*DH)      // 3840
#define ROWS   (BSZ*SEQ)      // 2048
#define NABC_ABC 2304         // a,b,c columns (1-pass ok)
#define NABC_DE  1536         // d,e columns (3-pass required)
#define STR    68             // padded fp32 smem row stride (floats)
#define BRS    144            // bf16 smem row stride in bytes

// ---------------- device scratch (allocation-free) ----------------
__device__ float g_abcde[ROWS * NABC];            // fp32, 31.5 MB
__device__ __nv_bfloat16 g_xh[ROWS * DM];
__device__ __nv_bfloat16 g_xl[ROWS * DM];
__device__ __nv_bfloat16 g_wth[NABC * DM];
__device__ __nv_bfloat16 g_wtl[NABC * DM];
__device__ __nv_bfloat16 g_woth[DM * DM];
__device__ __nv_bfloat16 g_wotl[DM * DM];
__device__ __nv_bfloat16 g_zh[ROWS * DM];
__device__ __nv_bfloat16 g_zl[ROWS * DM];

// ---------------- low-level helpers ----------------
__device__ __forceinline__ uint32_t smem_u32(const void* p) {
    uint32_t a;
    asm("{ .reg .u64 t; cvta.to.shared.u64 t, %1; cvt.u32.u64 %0, t; }"
        : "=r"(a) : "l"(p));
    return a;
}
__device__ __forceinline__ void cp_async16(uint32_t s, const void* g) {
    asm volatile("cp.async.cg.shared.global [%0], [%1], 16;"
                 :: "r"(s), "l"(g) : "memory");
}
__device__ __forceinline__ void cp_commit() {
    asm volatile("cp.async.commit_group;" ::: "memory");
}
__device__ __forceinline__ void cp_wait0() {
    asm volatile("cp.async.wait_group 0;" ::: "memory");
}
__device__ __forceinline__ void cp_wait1() {
    asm volatile("cp.async.wait_group 1;" ::: "memory");
}
__device__ __forceinline__ void ldm_x4(uint32_t* r, uint32_t a) {
    asm volatile("ldmatrix.sync.aligned.m8n8.x4.shared.b16 {%0,%1,%2,%3}, [%4];"
                 : "=r"(r[0]), "=r"(r[1]), "=r"(r[2]), "=r"(r[3]) : "r"(a));
}
__device__ __forceinline__ void mma_bf16(float* c, const uint32_t* a,
                                         const uint32_t* b) {
    asm volatile(
        "mma.sync.aligned.m16n8k16.row.col.f32.bf16.bf16.f32 "
        "{%0,%1,%2,%3}, {%4,%5,%6,%7}, {%8,%9}, {%0,%1,%2,%3};"
        : "+f"(c[0]), "+f"(c[1]), "+f"(c[2]), "+f"(c[3])
        : "r"(a[0]), "r"(a[1]), "r"(a[2]), "r"(a[3]), "r"(b[0]), "r"(b[1]));
}
__device__ __forceinline__ void sts64(uint32_t a, uint32_t x, uint32_t y) {
    asm volatile("st.shared.v2.b32 [%0], {%1,%2};"
                 :: "r"(a), "r"(x), "r"(y) : "memory");
}
__device__ __forceinline__ float ex2f(float x) {
    float r; asm("ex2.approx.f32 %0, %1;" : "=f"(r) : "f"(x)); return r;
}
__device__ __forceinline__ void split4(float4 v, uint32_t* hi, uint32_t* lo) {
    float f[4] = {v.x, v.y, v.z, v.w};
    uint32_t h[4], l[4];
    #pragma unroll
    for (int q = 0; q < 4; q++) {
        __nv_bfloat16 hb = __float2bfloat16(f[q]);
        __nv_bfloat16 lb = __float2bfloat16(f[q] - __bfloat162float(hb));
        h[q] = __bfloat16_as_ushort(hb);
        l[q] = __bfloat16_as_ushort(lb);
    }
    hi[0] = h[0] | (h[1] << 16); hi[1] = h[2] | (h[3] << 16);
    lo[0] = l[0] | (l[1] << 16); lo[1] = l[2] | (l[3] << 16);
}
__device__ __forceinline__ uint32_t pack_bf16x2(float a, float b) {
    __nv_bfloat162 p = __float22bfloat162_rn(make_float2(a, b));
    return *(uint32_t*)&p;
}

// ---------------------------------------------------------------------------
// 3-pass bf16x3 GEMM (proven).
// ---------------------------------------------------------------------------
#define RS 144
#define MAT_BYTES (128 * RS)
#define STAGE_BYTES (4 * MAT_BYTES)
#define GEMM_SMEM (3 * STAGE_BYTES)

__device__ __forceinline__ void gm_issue_stage(
    const __nv_bfloat16* __restrict__ Ah, const __nv_bfloat16* __restrict__ Al,
    const __nv_bfloat16* __restrict__ Bh, const __nv_bfloat16* __restrict__ Bl,
    int K, int bm, int bn, int k0, uint32_t base, int tid)
{
    #pragma unroll
    for (int r = 0; r < 16; r++) {
        const int cid = tid + r * 256;
        const int mat = cid >> 10;
        const int row = (cid >> 3) & 127;
        const int seg = cid & 7;
        const uint32_t sa = base + mat * MAT_BYTES + row * RS + seg * 16;
        const __nv_bfloat16* src;
        if (mat == 0)      src = Ah + (size_t)(bm + row) * K + k0 + seg * 8;
        else if (mat == 1) src = Al + (size_t)(bm + row) * K + k0 + seg * 8;
        else if (mat == 2) src = Bh + (size_t)(bn + row) * K + k0 + seg * 8;
        else               src = Bl + (size_t)(bn + row) * K + k0 + seg * 8;
        cp_async16(sa, src);
    }
    cp_commit();
}

__global__ void __launch_bounds__(256, 1) tc_gemm_kernel(
    const __nv_bfloat16* __restrict__ Ah, const __nv_bfloat16* __restrict__ Al,
    const __nv_bfloat16* __restrict__ Bh, const __nv_bfloat16* __restrict__ Bl,
    const float* __restrict__ bias, float* __restrict__ C,
    int ldc, int K)
{
    extern __shared__ char dsm[];
    const uint32_t sbase = smem_u32(dsm);

    const int tid = threadIdx.x;
    const int wid = tid >> 5, lane = tid & 31;
    const int warp_m = wid >> 2;
    const int warp_n = wid & 3;
    const int bm = blockIdx.y * 128, bn = blockIdx.x * 128;

    const int lr = lane & 7, part = lane >> 3;
    const int a_row_off = lr + (part & 1) * 8;
    const int a_kb_off  = (part >> 1) * 16;
    const int b_row_off = lr + (part >> 1) * 8;
    const int b_kb_off  = (part & 1) * 16;

    float acc[4][4][4] = {};
    const int NCHUNK = K >> 6;

    gm_issue_stage(Ah, Al, Bh, Bl, K, bm, bn, 0, sbase, tid);
    if (NCHUNK > 1)
        gm_issue_stage(Ah, Al, Bh, Bl, K, bm, bn, 64, sbase + STAGE_BYTES, tid);

    for (int c = 0; c < NCHUNK; c++) {
        if (c + 1 < NCHUNK) cp_wait1(); else cp_wait0();
        __syncthreads();
        if (c + 2 < NCHUNK) {
            const int st = (c + 2) % 3;
            gm_issue_stage(Ah, Al, Bh, Bl, K, bm, bn, (c + 2) * 64,
                           sbase + (uint32_t)st * STAGE_BYTES, tid);
        }
        const uint32_t cur = sbase + (uint32_t)(c % 3) * STAGE_BYTES;
        const uint32_t sAh = cur;
        const uint32_t sAl = cur + MAT_BYTES;
        const uint32_t sBh = cur + 2 * MAT_BYTES;
        const uint32_t sBl = cur + 3 * MAT_BYTES;

        #pragma unroll
        for (int s = 0; s < 4; s++) {
            const int kb = s * 32;
            uint32_t fAh[4][4], fAl[4][4];
            #pragma unroll
            for (int mt = 0; mt < 4; mt++) {
                const int row = warp_m * 64 + mt * 16 + a_row_off;
                ldm_x4(fAh[mt], sAh + row * RS + kb + a_kb_off);
                ldm_x4(fAl[mt], sAl + row * RS + kb + a_kb_off);
            }
            uint32_t fBh[2][4], fBl[2][4];
            #pragma unroll
            for (int g = 0; g < 2; g++) {
                const int row = warp_n * 32 + g * 16 + b_row_off;
                ldm_x4(fBh[g], sBh + row * RS + kb + b_kb_off);
                ldm_x4(fBl[g], sBl + row * RS + kb + b_kb_off);
            }
            #pragma unroll
            for (int mt = 0; mt < 4; mt++)
                #pragma unroll
                for (int g = 0; g < 2; g++)
                    #pragma unroll
                    for (int h2 = 0; h2 < 2; h2++)
                        mma_bf16(acc[mt][g * 2 + h2], fAh[mt], fBh[g] + h2 * 2);
            #pragma unroll
            for (int mt = 0; mt < 4; mt++)
                #pragma unroll
                for (int g = 0; g < 2; g++)
                    #pragma unroll
                    for (int h2 = 0; h2 < 2; h2++)
                        mma_bf16(acc[mt][g * 2 + h2], fAh[mt], fBl[g] + h2 * 2);
            #pragma unroll
            for (int mt = 0; mt < 4; mt++)
                #pragma unroll
                for (int g = 0; g < 2; g++)
                    #pragma unroll
                    for (int h2 = 0; h2 < 2; h2++)
                        mma_bf16(acc[mt][g * 2 + h2], fAl[mt], fBh[g] + h2 * 2);
        }
    }

    const int gq = lane >> 2, tq = lane & 3;
    #pragma unroll
    for (int mt = 0; mt < 4; mt++) {
        const int r0 = bm + warp_m * 64 + mt * 16 + gq;
        #pragma unroll
        for (int nt = 0; nt < 4; nt++) {
            const int col = bn + warp_n * 32 + nt * 8 + tq * 2;
            const float2 bv = *(const float2*)&bias[col];
            float2 v0 = make_float2(acc[mt][nt][0] + bv.x, acc[mt][nt][1] + bv.y);
            float2 v1 = make_float2(acc[mt][nt][2] + bv.x, acc[mt][nt][3] + bv.y);
            *(float2*)&C[(size_t)r0 * ldc + col] = v0;
            *(float2*)&C[(size_t)(r0 + 8) * ldc + col] = v1;
        }
    }
}

// ---------------------------------------------------------------------------
// 1-pass plain-bf16 GEMM (a,b,c columns)
// ---------------------------------------------------------------------------
#define STAGE1_BYTES (2 * MAT_BYTES)
#define GEMM1_SMEM (3 * STAGE1_BYTES)

__device__ __forceinline__ void gm1_issue_stage(
    const __nv_bfloat16* __restrict__ A, const __nv_bfloat16* __restrict__ B,
    int K, int bm, int bn, int k0, uint32_t base, int tid)
{
    #pragma unroll
    for (int r = 0; r < 8; r++) {
        const int cid = tid + r * 256;
        const int mat = cid >> 10;
        const int row = (cid >> 3) & 127;
        const int seg = cid & 7;
        const uint32_t sa = base + mat * MAT_BYTES + row * RS + seg * 16;
        const __nv_bfloat16* src = (mat == 0)
            ? A + (size_t)(bm + row) * K + k0 + seg * 8
            : B + (size_t)(bn + row) * K + k0 + seg * 8;
        cp_async16(sa, src);
    }
    cp_commit();
}

__global__ void __launch_bounds__(256, 1) tc_gemm1_kernel(
    const __nv_bfloat16* __restrict__ A, const __nv_bfloat16* __restrict__ B,
    const float* __restrict__ bias, float* __restrict__ C,
    int ldc, int K)
{
    extern __shared__ char dsm[];
    const uint32_t sbase = smem_u32(dsm);

    const int tid = threadIdx.x;
    const int wid = tid >> 5, lane = tid & 31;
    const int warp_m = wid >> 2;
    const int warp_n = wid & 3;
    const int bm = blockIdx.y * 128, bn = blockIdx.x * 128;

    const int lr = lane & 7, part = lane >> 3;
    const int a_row_off = lr + (part & 1) * 8;
    const int a_kb_off  = (part >> 1) * 16;
    const int b_row_off = lr + (part >> 1) * 8;
    const int b_kb_off  = (part & 1) * 16;

    float acc[4][4][4] = {};
    const int NCHUNK = K >> 6;

    gm1_issue_stage(A, B, K, bm, bn, 0, sbase, tid);
    if (NCHUNK > 1)
        gm1_issue_stage(A, B, K, bm, bn, 64, sbase + STAGE1_BYTES, tid);

    for (int c = 0; c < NCHUNK; c++) {
        if (c + 1 < NCHUNK) cp_wait1(); else cp_wait0();
        __syncthreads();
        if (c + 2 < NCHUNK) {
            const int st = (c + 2) % 3;
            gm1_issue_stage(A, B, K, bm, bn, (c + 2) * 64,
                            sbase + (uint32_t)st * STAGE1_BYTES, tid);
        }
        const uint32_t cur = sbase + (uint32_t)(c % 3) * STAGE1_BYTES;
        const uint32_t sA = cur;
        const uint32_t sB = cur + MAT_BYTES;

        #pragma unroll
        for (int s = 0; s < 4; s++) {
            const int kb = s * 32;
            uint32_t fA[4][4];
            #pragma unroll
            for (int mt = 0; mt < 4; mt++) {
                const int row = warp_m * 64 + mt * 16 + a_row_off;
                ldm_x4(fA[mt], sA + row * RS + kb + a_kb_off);
            }
            uint32_t fB[2][4];
            #pragma unroll
            for (int g = 0; g < 2; g++) {
                const int row = warp_n * 32 + g * 16 + b_row_off;
                ldm_x4(fB[g], sB + row * RS + kb + b_kb_off);
            }
            #pragma unroll
            for (int mt = 0; mt < 4; mt++)
                #pragma unroll
                for (int g = 0; g < 2; g++)
                    #pragma unroll
                    for (int h2 = 0; h2 < 2; h2++)
                        mma_bf16(acc[mt][g * 2 + h2], fA[mt], fB[g] + h2 * 2);
        }
    }

    const int gq = lane >> 2, tq = lane & 3;
    #pragma unroll
    for (int mt = 0; mt < 4; mt++) {
        const int r0 = bm + warp_m * 64 + mt * 16 + gq;
        #pragma unroll
        for (int nt = 0; nt < 4; nt++) {
            const int col = bn + warp_n * 32 + nt * 8 + tq * 2;
            const float2 bv = *(const float2*)&bias[col];
            float2 v0 = make_float2(acc[mt][nt][0] + bv.x, acc[mt][nt][1] + bv.y);
            float2 v1 = make_float2(acc[mt][nt][2] + bv.x, acc[mt][nt][3] + bv.y);
            *(float2*)&C[(size_t)r0 * ldc + col] = v0;
            *(float2*)&C[(size_t)(r0 + 8) * ldc + col] = v1;
        }
    }
}

// ---------------------------------------------------------------------------
// merged prep
// ---------------------------------------------------------------------------
#define PREP_B1 ((NABC/32)*(DM/32))          // 2880
#define PREP_B2 ((DM/32)*(DM/32))            // 576
#define PREP_B3 (ROWS * DM / 4 / 256)        // 1536
#define PREP_GRID (PREP_B1 + PREP_B2 + PREP_B3)

__device__ __forceinline__ void transpose_tile(
    const float* __restrict__ W, __nv_bfloat16* __restrict__ Th,
    __nv_bfloat16* __restrict__ Tl, int K, int N, int bx, int by, int tid,
    float (*t)[33])
{
    const int n0 = bx * 32, k0 = by * 32;
    const int tx = tid & 31, ty = tid >> 5;
    for (int r = ty; r < 32; r += 8)
        t[r][tx] = W[(size_t)(k0 + r) * N + n0 + tx];
    __syncthreads();
    for (int r = ty; r < 32; r += 8) {
        const float v = t[tx][r];
        const __nv_bfloat16 h = __float2bfloat16(v);
        const __nv_bfloat16 l = __float2bfloat16(v - __bfloat162float(h));
        Th[(size_t)(n0 + r) * K + k0 + tx] = h;
        Tl[(size_t)(n0 + r) * K + k0 + tx] = l;
    }
}

__global__ void __launch_bounds__(256) prep_kernel(
    const float* __restrict__ Wab, const float* __restrict__ WO,
    const float* __restrict__ x,
    __nv_bfloat16* __restrict__ wth, __nv_bfloat16* __restrict__ wtl,
    __nv_bfloat16* __restrict__ woth, __nv_bfloat16* __restrict__ wotl,
    __nv_bfloat16* __restrict__ xh, __nv_bfloat16* __restrict__ xl)
{
    __shared__ float t[32][33];
    int bid = blockIdx.x;
    const int tid = threadIdx.x;
    if (bid < PREP_B1) {
        transpose_tile(Wab, wth, wtl, DM, NABC, bid % (NABC/32), bid / (NABC/32),
                       tid, t);
    } else if (bid < PREP_B1 + PREP_B2) {
        bid -= PREP_B1;
        transpose_tile(WO, woth, wotl, DM, DM, bid % (DM/32), bid / (DM/32),
                       tid, t);
    } else {
        bid -= PREP_B1 + PREP_B2;
        const int i = bid * 256 + tid;
        float4 v = ((const float4*)x)[i];
        uint32_t hx[2], lx[2];
        split4(v, hx, lx);
        ((uint2*)xh)[i] = make_uint2(hx[0], hx[1]);
        ((uint2*)xl)[i] = make_uint2(lx[0], lx[1]);
    }
}

// ---------------------------------------------------------------------------
// Tensor-core local trittention v11:
//  - warp = 16-j strip x FULL 64-k (strips 0-3, isel 0-1): no duplicated
//    A-fragment work, Sj via plain stores (no atomics)
//  - static mask as 32-bit bitmask; dynamic mask k > 32+half*16+ilw
//  - fused exp constant (1 FMUL + MUFU per element)
// ---------------------------------------------------------------------------
#define FOFF3 (240 * STR + 32)
#define ATTN_SMEM (FOFF3 * 4 + 64 * BRS)     // 74624 B
#define EXC 0.02254170249359f                // log2(e)/64

__global__ void __launch_bounds__(256, 2) attn_kernel(
    const float* __restrict__ abcde,
    __nv_bfloat16* __restrict__ zh, __nv_bfloat16* __restrict__ zl)
{
    extern __shared__ float sm[];
    float* sc  = sm;                     // 16*STR
    float* sa  = sc  + 16 * STR;         // 64*STR
    float* sd  = sa  + 64 * STR;         // 64*STR
    float* se  = sd  + 64 * STR;         // 64*STR
    float* SjM = se  + 64 * STR;         // 16*STR
    float* SkM = SjM + 16 * STR;         // 16*STR
    float* red = SkM + 16 * STR;         // 32

    const uint32_t sbase = smem_u32(sm);
    const uint32_t sbh   = sbase + FOFF3 * 4;

    const int blk  = blockIdx.x;
    const int half = blk & 1;
    const int w    = (blk >> 1) & (NW - 1);
    const int hb   = blk >> 6;
    const int h    = hb % NH;
    const int b    = hb / NH;
    const int tid  = threadIdx.x;
    const int baseRow = b * SEQ + w * WIN;

    {
        const int i = tid >> 4, dq = (tid & 15) << 2;
        float4 v = *(const float4*)&abcde[
            (size_t)(baseRow + half * 16 + i) * NABC + (2 * NH + h) * DH + dq];
        *(float4*)&sc[i * STR + dq] = v;
    }
    for (int p = tid; p < 64 * 16; p += 256) {
        const int jj = p >> 4, dq = (p & 15) << 2;
        float4 z4 = make_float4(0.f, 0.f, 0.f, 0.f);
        float4 va = z4, vb = z4, vd = z4, ve = z4;
        if (w > 0 || jj >= 32) {
            const size_t r = (size_t)(baseRow - 32 + jj) * NABC;
            va = *(const float4*)&abcde[r + (0 * NH + h) * DH + dq];
            vb = *(const float4*)&abcde[r + (1 * NH + h) * DH + dq];
            vd = *(const float4*)&abcde[r + (3 * NH + h) * DH + dq];
            ve = *(const float4*)&abcde[r + (4 * NH + h) * DH + dq];
        }
        *(float4*)&sa[jj * STR + dq] = va;
        *(float4*)&sd[jj * STR + dq] = vd;
        *(float4*)&se[jj * STR + dq] = ve;
        sts64(sbh + jj * BRS + dq * 2,
              pack_bf16x2(vb.x, vb.y), pack_bf16x2(vb.z, vb.w));
    }
    for (int p = tid; p < 32 * STR; p += 256) SjM[p] = 0.f;
    __syncthreads();

    // ---- warp / lane geometry: strip (4) x isel (2) ----
    const int wid = tid >> 5, lane = tid & 31;
    const int strip = wid & 3;           // j strip: [16*strip, 16*strip+16)
    const int isel  = wid >> 2;          // which of the 2 rows per t
    const int lr = lane & 7, part = lane >> 3;
    const int gq = lane >> 2, tq = lane & 3;

    const uint32_t b_frag_base =
        (uint32_t)((lr + (part >> 1) * 8) * BRS + (part & 1) * 16);
    const int ja = 16 * strip + gq;      // j for rg 0/1 (rg 2/3: ja+8)

    // static mask bitmask: bit = jsel*16 + nt*2 + e  <=>  pk <= pj
    uint32_t mstat = 0;
    #pragma unroll
    for (int jsel = 0; jsel < 2; jsel++) {
        const int j = ja + jsel * 8;
        const int pj = (w == 0 && j < 32) ? 0 : (w * WIN - WIN + j);
        #pragma unroll
        for (int nt = 0; nt < 8; nt++)
            #pragma unroll
            for (int e = 0; e < 2; e++) {
                const int k = nt * 8 + tq * 2 + e;
                const int pk = (w == 0 && k < 32) ? 0 : (w * WIN - WIN + k);
                if (pk <= pj) mstat |= 1u << (jsel * 16 + nt * 2 + e);
            }
    }

    // ---- barrier-free main loop: 8 iterations x 2 query rows ----
    for (int t = 0; t < 8; t++) {
        const int ilw  = t * 2 + isel;               // warp's local row
        const int kthr = 32 + half * 16 + ilw;       // dynamic mask threshold

        float acc[8][4] = {};
        #pragma unroll
        for (int s = 0; s < 4; s++) {
            const int kc = s * 16 + tq * 2;
            const float2 cc0 = *(const float2*)&sc[ilw * STR + kc];
            const float2 cc8 = *(const float2*)&sc[ilw * STR + kc + 8];
            const float2 aA = *(const float2*)&sa[ja * STR + kc];
            const float2 aB = *(const float2*)&sa[(ja + 8) * STR + kc];
            const float2 aC = *(const float2*)&sa[ja * STR + kc + 8];
            const float2 aD = *(const float2*)&sa[(ja + 8) * STR + kc + 8];
            uint32_t fA[4];
            fA[0] = pack_bf16x2(aA.x * cc0.x, aA.y * cc0.y);
            fA[1] = pack_bf16x2(aB.x * cc0.x, aB.y * cc0.y);
            fA[2] = pack_bf16x2(aC.x * cc8.x, aC.y * cc8.y);
            fA[3] = pack_bf16x2(aD.x * cc8.x, aD.y * cc8.y);

            uint32_t fB[4][4];
            #pragma unroll
            for (int g = 0; g < 4; g++)
                ldm_x4(fB[g], sbh + b_frag_base + g * 16 * BRS + s * 32);

            #pragma unroll
            for (int g = 0; g < 4; g++)
                #pragma unroll
                for (int h2 = 0; h2 < 2; h2++)
                    mma_bf16(acc[g * 2 + h2], fA, fB[g] + h2 * 2);
        }

        // mask + exp (fused constant)
        #pragma unroll
        for (int nt = 0; nt < 8; nt++)
            #pragma unroll
            for (int rg = 0; rg < 4; rg++) {
                const int e = rg & 1, jsel = rg >> 1;
                const int k = nt * 8 + tq * 2 + e;
                const float v = acc[nt][rg];
                const bool m = (k > kthr)
                             | ((mstat >> (jsel * 16 + nt * 2 + e)) & 1u)
                             | (v == 0.0f);
                acc[nt][rg] = m ? 0.0f : ex2f(v * EXC);
            }

        // Sj (full-k sums per warp): quad shuffles + PLAIN STORES
        {
            float s0 = 0.f, s1 = 0.f;
            #pragma unroll
            for (int nt = 0; nt < 8; nt++) {
                s0 += acc[nt][0] + acc[nt][1];
                s1 += acc[nt][2] + acc[nt][3];
            }
            s0 += __shfl_xor_sync(0xffffffffu, s0, 1);
            s1 += __shfl_xor_sync(0xffffffffu, s1, 1);
            s0 += __shfl_xor_sync(0xffffffffu, s0, 2);
            s1 += __shfl_xor_sync(0xffffffffu, s1, 2);
            if (tq == 0) {
                SjM[ilw * STR + ja] = s0;
                SjM[ilw * STR + ja + 8] = s1;
            }
        }
        // Sk: xor 4/8/16 shuffles + atomics (4 strips contend)
        {
            float t0[8], t1[8];
            #pragma unroll
            for (int nt = 0; nt < 8; nt++) {
                t0[nt] = acc[nt][0] + acc[nt][2];
                t1[nt] = acc[nt][1] + acc[nt][3];
            }
            #pragma unroll
            for (int o = 4; o <= 16; o <<= 1)
                #pragma unroll
                for (int nt = 0; nt < 8; nt++) {
                    t0[nt] += __shfl_xor_sync(0xffffffffu, t0[nt], o);
                    t1[nt] += __shfl_xor_sync(0xffffffffu, t1[nt], o);
                }
            if (gq == 0) {
                #pragma unroll
                for (int nt = 0; nt < 8; nt++) {
                    const int k = nt * 8 + tq * 2;
                    atomicAdd(&SkM[ilw * STR + k],     t0[nt]);
                    atomicAdd(&SkM[ilw * STR + k + 1], t1[nt]);
                }
            }
        }
    }
    __syncthreads();

    if (tid < 16) {
        const float* r = &SjM[tid * STR];
        float s = 0.f;
        #pragma unroll 8
        for (int j = 0; j < 64; j++) s += r[j];
        red[tid] = (s > 0.f) ? (1.0f / s) : -1.0f;
    }
    __syncthreads();

    // epilogue: Z[16,64] = norm(SjM) @ sd + norm(SkM) @ se (fp32 d/e)
    {
        const int il = tid >> 4;
        const int d0 = (tid & 15) << 2;
        const float invv = red[il];
        const bool  uni  = (invv < 0.f);
        const float uadd = uni ? 1.0f : 0.0f;
        const float fscl = uni ? (1.0f / 64.0f) : invv;
        float z[4] = {};
        #pragma unroll 4
        for (int j = 0; j < 64; j++) {
            const float sj = SjM[il * STR + j] + uadd;
            const float sk = SkM[il * STR + j] + uadd;
            float4 dA = *(const float4*)&sd[j * STR + d0];
            float4 eA = *(const float4*)&se[j * STR + d0];
            z[0] = fmaf(sj, dA.x, z[0]); z[1] = fmaf(sj, dA.y, z[1]);
            z[2] = fmaf(sj, dA.z, z[2]); z[3] = fmaf(sj, dA.w, z[3]);
            z[0] = fmaf(sk, eA.x, z[0]); z[1] = fmaf(sk, eA.y, z[1]);
            z[2] = fmaf(sk, eA.z, z[2]); z[3] = fmaf(sk, eA.w, z[3]);
        }
        uint32_t uh[2], ul[2];
        #pragma unroll
        for (int q = 0; q < 2; q++) {
            const float f0 = z[2 * q] * fscl, f1 = z[2 * q + 1] * fscl;
            __nv_bfloat16 h0 = __float2bfloat16(f0);
            __nv_bfloat16 h1 = __float2bfloat16(f1);
            __nv_bfloat16 l0 = __float2bfloat16(f0 - __bfloat162float(h0));
            __nv_bfloat16 l1 = __float2bfloat16(f1 - __bfloat162float(h1));
            uh[q] = (uint32_t)__bfloat16_as_ushort(h0)
                  | ((uint32_t)__bfloat16_as_ushort(h1) << 16);
            ul[q] = (uint32_t)__bfloat16_as_ushort(l0)
                  | ((uint32_t)__bfloat16_as_ushort(l1) << 16);
        }
        const size_t off =
            (size_t)(baseRow + half * 16 + il) * DM + h * DH + d0;
        *(uint2*)(zh + off) = make_uint2(uh[0], uh[1]);
        *(uint2*)(zl + off) = make_uint2(ul[0], ul[1]);
    }
}

// ---------------------------------------------------------------------------
extern "C" void kernel_launch(void* const* d_in, const int* in_sizes, int n_in,
                              void* d_out, int out_size)
{
    const float* x   = (const float*)d_in[0];
    const float* Wab = (const float*)d_in[1];
    const float* bab = (const float*)d_in[2];
    const float* WO  = (const float*)d_in[3];
    const float* bO  = (const float*)d_in[4];
    float* out = (float*)d_out;

    float* abcde_p = nullptr;
    __nv_bfloat16 *xh, *xl, *wth, *wtl, *woth, *wotl, *zh, *zl;
    cudaGetSymbolAddress((void**)&abcde_p, g_abcde);
    cudaGetSymbolAddress((void**)&xh,   g_xh);
    cudaGetSymbolAddress((void**)&xl,   g_xl);
    cudaGetSymbolAddress((void**)&wth,  g_wth);
    cudaGetSymbolAddress((void**)&wtl,  g_wtl);
    cudaGetSymbolAddress((void**)&woth, g_woth);
    cudaGetSymbolAddress((void**)&wotl, g_wotl);
    cudaGetSymbolAddress((void**)&zh,   g_zh);
    cudaGetSymbolAddress((void**)&zl,   g_zl);

    cudaFuncSetAttribute(tc_gemm_kernel,
                         cudaFuncAttributeMaxDynamicSharedMemorySize, GEMM_SMEM);
    cudaFuncSetAttribute(tc_gemm1_kernel,
                         cudaFuncAttributeMaxDynamicSharedMemorySize, GEMM1_SMEM);
    cudaFuncSetAttribute(attn_kernel,
                         cudaFuncAttributeMaxDynamicSharedMemorySize, ATTN_SMEM);

    prep_kernel<<<PREP_GRID, 256>>>(Wab, WO, x, wth, wtl, woth, wotl, xh, xl);

    tc_gemm1_kernel<<<dim3(NABC_ABC / 128, ROWS / 128), 256, GEMM1_SMEM>>>(
        xh, wth, bab, abcde_p, NABC, DM);

    tc_gemm_kernel<<<dim3(NABC_DE / 128, ROWS / 128), 256, GEMM_SMEM>>>(
        xh, xl, wth + (size_t)NABC_ABC * DM, wtl + (size_t)NABC_ABC * DM,
        bab + NABC_ABC, abcde_p + NABC_ABC, NABC, DM);

    attn_kernel<<<BSZ * NH * NW * 2, 256, ATTN_SMEM>>>(abcde_p, zh, zl);

    tc_gemm_kernel<<<dim3(DM / 128, ROWS / 128), 256, GEMM_SMEM>>>(
        zh, zl, woth, wotl, bO, out, DM, DM);
}

// round 16
// speedup vs baseline: 1.0296x; 1.0296x over previous
#include <cuda_runtime.h>
#include <cuda_bf16.h>
#include <cstdint>

#define SEQ    1024
#define BSZ    2
#define DM     768
#define NH     12
#define DH     64
#define WIN    32
#define NW     (SEQ/WIN)
#define NABC   (5*NH*DH)      // 3840
#define ROWS   (BSZ*SEQ)      // 2048
#define NABC_ABC 2304         // a,b,c columns (1-pass ok)
#define NABC_DE  1536         // d,e columns (3-pass required)
#define STR    68             // padded fp32 smem row stride (floats)
#define BRS    144            // bf16 smem row stride in bytes

// ---------------- device scratch (allocation-free) ----------------
__device__ float g_abcde[ROWS * NABC];            // fp32, 31.5 MB
__device__ __nv_bfloat16 g_xh[ROWS * DM];
__device__ __nv_bfloat16 g_xl[ROWS * DM];
__device__ __nv_bfloat16 g_wth[NABC * DM];
__device__ __nv_bfloat16 g_wtl[NABC * DM];
__device__ __nv_bfloat16 g_woth[DM * DM];
__device__ __nv_bfloat16 g_wotl[DM * DM];
__device__ __nv_bfloat16 g_zh[ROWS * DM];
__device__ __nv_bfloat16 g_zl[ROWS * DM];

// ---------------- low-level helpers ----------------
__device__ __forceinline__ uint32_t smem_u32(const void* p) {
    uint32_t a;
    asm("{ .reg .u64 t; cvta.to.shared.u64 t, %1; cvt.u32.u64 %0, t; }"
        : "=r"(a) : "l"(p));
    return a;
}
__device__ __forceinline__ void cp_async16(uint32_t s, const void* g) {
    asm volatile("cp.async.cg.shared.global [%0], [%1], 16;"
                 :: "r"(s), "l"(g) : "memory");
}
__device__ __forceinline__ void cp_commit() {
    asm volatile("cp.async.commit_group;" ::: "memory");
}
__device__ __forceinline__ void cp_wait0() {
    asm volatile("cp.async.wait_group 0;" ::: "memory");
}
__device__ __forceinline__ void cp_wait1() {
    asm volatile("cp.async.wait_group 1;" ::: "memory");
}
__device__ __forceinline__ void ldm_x4(uint32_t* r, uint32_t a) {
    asm volatile("ldmatrix.sync.aligned.m8n8.x4.shared.b16 {%0,%1,%2,%3}, [%4];"
                 : "=r"(r[0]), "=r"(r[1]), "=r"(r[2]), "=r"(r[3]) : "r"(a));
}
__device__ __forceinline__ void mma_bf16(float* c, const uint32_t* a,
                                         const uint32_t* b) {
    asm volatile(
        "mma.sync.aligned.m16n8k16.row.col.f32.bf16.bf16.f32 "
        "{%0,%1,%2,%3}, {%4,%5,%6,%7}, {%8,%9}, {%0,%1,%2,%3};"
        : "+f"(c[0]), "+f"(c[1]), "+f"(c[2]), "+f"(c[3])
        : "r"(a[0]), "r"(a[1]), "r"(a[2]), "r"(a[3]), "r"(b[0]), "r"(b[1]));
}
__device__ __forceinline__ void sts64(uint32_t a, uint32_t x, uint32_t y) {
    asm volatile("st.shared.v2.b32 [%0], {%1,%2};"
                 :: "r"(a), "r"(x), "r"(y) : "memory");
}
__device__ __forceinline__ float ex2f(float x) {
    float r; asm("ex2.approx.f32 %0, %1;" : "=f"(r) : "f"(x)); return r;
}
__device__ __forceinline__ void split4(float4 v, uint32_t* hi, uint32_t* lo) {
    float f[4] = {v.x, v.y, v.z, v.w};
    uint32_t h[4], l[4];
    #pragma unroll
    for (int q = 0; q < 4; q++) {
        __nv_bfloat16 hb = __float2bfloat16(f[q]);
        __nv_bfloat16 lb = __float2bfloat16(f[q] - __bfloat162float(hb));
        h[q] = __bfloat16_as_ushort(hb);
        l[q] = __bfloat16_as_ushort(lb);
    }
    hi[0] = h[0] | (h[1] << 16); hi[1] = h[2] | (h[3] << 16);
    lo[0] = l[0] | (l[1] << 16); lo[1] = l[2] | (l[3] << 16);
}
__device__ __forceinline__ uint32_t pack_bf16x2(float a, float b) {
    __nv_bfloat162 p = __float22bfloat162_rn(make_float2(a, b));
    return *(uint32_t*)&p;
}

// ---------------------------------------------------------------------------
// 3-pass bf16x3 GEMM (proven).
// ---------------------------------------------------------------------------
#define RS 144
#define MAT_BYTES (128 * RS)
#define STAGE_BYTES (4 * MAT_BYTES)
#define GEMM_SMEM (3 * STAGE_BYTES)

__device__ __forceinline__ void gm_issue_stage(
    const __nv_bfloat16* __restrict__ Ah, const __nv_bfloat16* __restrict__ Al,
    const __nv_bfloat16* __restrict__ Bh, const __nv_bfloat16* __restrict__ Bl,
    int K, int bm, int bn, int k0, uint32_t base, int tid)
{
    #pragma unroll
    for (int r = 0; r < 16; r++) {
        const int cid = tid + r * 256;
        const int mat = cid >> 10;
        const int row = (cid >> 3) & 127;
        const int seg = cid & 7;
        const uint32_t sa = base + mat * MAT_BYTES + row * RS + seg * 16;
        const __nv_bfloat16* src;
        if (mat == 0)      src = Ah + (size_t)(bm + row) * K + k0 + seg * 8;
        else if (mat == 1) src = Al + (size_t)(bm + row) * K + k0 + seg * 8;
        else if (mat == 2) src = Bh + (size_t)(bn + row) * K + k0 + seg * 8;
        else               src = Bl + (size_t)(bn + row) * K + k0 + seg * 8;
        cp_async16(sa, src);
    }
    cp_commit();
}

__global__ void __launch_bounds__(256, 1) tc_gemm_kernel(
    const __nv_bfloat16* __restrict__ Ah, const __nv_bfloat16* __restrict__ Al,
    const __nv_bfloat16* __restrict__ Bh, const __nv_bfloat16* __restrict__ Bl,
    const float* __restrict__ bias, float* __restrict__ C,
    int ldc, int K)
{
    extern __shared__ char dsm[];
    const uint32_t sbase = smem_u32(dsm);

    const int tid = threadIdx.x;
    const int wid = tid >> 5, lane = tid & 31;
    const int warp_m = wid >> 2;
    const int warp_n = wid & 3;
    const int bm = blockIdx.y * 128, bn = blockIdx.x * 128;

    const int lr = lane & 7, part = lane >> 3;
    const int a_row_off = lr + (part & 1) * 8;
    const int a_kb_off  = (part >> 1) * 16;
    const int b_row_off = lr + (part >> 1) * 8;
    const int b_kb_off  = (part & 1) * 16;

    float acc[4][4][4] = {};
    const int NCHUNK = K >> 6;

    gm_issue_stage(Ah, Al, Bh, Bl, K, bm, bn, 0, sbase, tid);
    if (NCHUNK > 1)
        gm_issue_stage(Ah, Al, Bh, Bl, K, bm, bn, 64, sbase + STAGE_BYTES, tid);

    for (int c = 0; c < NCHUNK; c++) {
        if (c + 1 < NCHUNK) cp_wait1(); else cp_wait0();
        __syncthreads();
        if (c + 2 < NCHUNK) {
            const int st = (c + 2) % 3;
            gm_issue_stage(Ah, Al, Bh, Bl, K, bm, bn, (c + 2) * 64,
                           sbase + (uint32_t)st * STAGE_BYTES, tid);
        }
        const uint32_t cur = sbase + (uint32_t)(c % 3) * STAGE_BYTES;
        const uint32_t sAh = cur;
        const uint32_t sAl = cur + MAT_BYTES;
        const uint32_t sBh = cur + 2 * MAT_BYTES;
        const uint32_t sBl = cur + 3 * MAT_BYTES;

        #pragma unroll
        for (int s = 0; s < 4; s++) {
            const int kb = s * 32;
            uint32_t fAh[4][4], fAl[4][4];
            #pragma unroll
            for (int mt = 0; mt < 4; mt++) {
                const int row = warp_m * 64 + mt * 16 + a_row_off;
                ldm_x4(fAh[mt], sAh + row * RS + kb + a_kb_off);
                ldm_x4(fAl[mt], sAl + row * RS + kb + a_kb_off);
            }
            uint32_t fBh[2][4], fBl[2][4];
            #pragma unroll
            for (int g = 0; g < 2; g++) {
                const int row = warp_n * 32 + g * 16 + b_row_off;
                ldm_x4(fBh[g], sBh + row * RS + kb + b_kb_off);
                ldm_x4(fBl[g], sBl + row * RS + kb + b_kb_off);
            }
            #pragma unroll
            for (int mt = 0; mt < 4; mt++)
                #pragma unroll
                for (int g = 0; g < 2; g++)
                    #pragma unroll
                    for (int h2 = 0; h2 < 2; h2++)
                        mma_bf16(acc[mt][g * 2 + h2], fAh[mt], fBh[g] + h2 * 2);
            #pragma unroll
            for (int mt = 0; mt < 4; mt++)
                #pragma unroll
                for (int g = 0; g < 2; g++)
                    #pragma unroll
                    for (int h2 = 0; h2 < 2; h2++)
                        mma_bf16(acc[mt][g * 2 + h2], fAh[mt], fBl[g] + h2 * 2);
            #pragma unroll
            for (int mt = 0; mt < 4; mt++)
                #pragma unroll
                for (int g = 0; g < 2; g++)
                    #pragma unroll
                    for (int h2 = 0; h2 < 2; h2++)
                        mma_bf16(acc[mt][g * 2 + h2], fAl[mt], fBh[g] + h2 * 2);
        }
    }

    const int gq = lane >> 2, tq = lane & 3;
    #pragma unroll
    for (int mt = 0; mt < 4; mt++) {
        const int r0 = bm + warp_m * 64 + mt * 16 + gq;
        #pragma unroll
        for (int nt = 0; nt < 4; nt++) {
            const int col = bn + warp_n * 32 + nt * 8 + tq * 2;
            const float2 bv = *(const float2*)&bias[col];
            float2 v0 = make_float2(acc[mt][nt][0] + bv.x, acc[mt][nt][1] + bv.y);
            float2 v1 = make_float2(acc[mt][nt][2] + bv.x, acc[mt][nt][3] + bv.y);
            *(float2*)&C[(size_t)r0 * ldc + col] = v0;
            *(float2*)&C[(size_t)(r0 + 8) * ldc + col] = v1;
        }
    }
}

// ---------------------------------------------------------------------------
// 1-pass plain-bf16 GEMM (a,b,c columns)
// ---------------------------------------------------------------------------
#define STAGE1_BYTES (2 * MAT_BYTES)
#define GEMM1_SMEM (3 * STAGE1_BYTES)

__device__ __forceinline__ void gm1_issue_stage(
    const __nv_bfloat16* __restrict__ A, const __nv_bfloat16* __restrict__ B,
    int K, int bm, int bn, int k0, uint32_t base, int tid)
{
    #pragma unroll
    for (int r = 0; r < 8; r++) {
        const int cid = tid + r * 256;
        const int mat = cid >> 10;
        const int row = (cid >> 3) & 127;
        const int seg = cid & 7;
        const uint32_t sa = base + mat * MAT_BYTES + row * RS + seg * 16;
        const __nv_bfloat16* src = (mat == 0)
            ? A + (size_t)(bm + row) * K + k0 + seg * 8
            : B + (size_t)(bn + row) * K + k0 + seg * 8;
        cp_async16(sa, src);
    }
    cp_commit();
}

__global__ void __launch_bounds__(256, 1) tc_gemm1_kernel(
    const __nv_bfloat16* __restrict__ A, const __nv_bfloat16* __restrict__ B,
    const float* __restrict__ bias, float* __restrict__ C,
    int ldc, int K)
{
    extern __shared__ char dsm[];
    const uint32_t sbase = smem_u32(dsm);

    const int tid = threadIdx.x;
    const int wid = tid >> 5, lane = tid & 31;
    const int warp_m = wid >> 2;
    const int warp_n = wid & 3;
    const int bm = blockIdx.y * 128, bn = blockIdx.x * 128;

    const int lr = lane & 7, part = lane >> 3;
    const int a_row_off = lr + (part & 1) * 8;
    const int a_kb_off  = (part >> 1) * 16;
    const int b_row_off = lr + (part >> 1) * 8;
    const int b_kb_off  = (part & 1) * 16;

    float acc[4][4][4] = {};
    const int NCHUNK = K >> 6;

    gm1_issue_stage(A, B, K, bm, bn, 0, sbase, tid);
    if (NCHUNK > 1)
        gm1_issue_stage(A, B, K, bm, bn, 64, sbase + STAGE1_BYTES, tid);

    for (int c = 0; c < NCHUNK; c++) {
        if (c + 1 < NCHUNK) cp_wait1(); else cp_wait0();
        __syncthreads();
        if (c + 2 < NCHUNK) {
            const int st = (c + 2) % 3;
            gm1_issue_stage(A, B, K, bm, bn, (c + 2) * 64,
                            sbase + (uint32_t)st * STAGE1_BYTES, tid);
        }
        const uint32_t cur = sbase + (uint32_t)(c % 3) * STAGE1_BYTES;
        const uint32_t sA = cur;
        const uint32_t sB = cur + MAT_BYTES;

        #pragma unroll
        for (int s = 0; s < 4; s++) {
            const int kb = s * 32;
            uint32_t fA[4][4];
            #pragma unroll
            for (int mt = 0; mt < 4; mt++) {
                const int row = warp_m * 64 + mt * 16 + a_row_off;
                ldm_x4(fA[mt], sA + row * RS + kb + a_kb_off);
            }
            uint32_t fB[2][4];
            #pragma unroll
            for (int g = 0; g < 2; g++) {
                const int row = warp_n * 32 + g * 16 + b_row_off;
                ldm_x4(fB[g], sB + row * RS + kb + b_kb_off);
            }
            #pragma unroll
            for (int mt = 0; mt < 4; mt++)
                #pragma unroll
                for (int g = 0; g < 2; g++)
                    #pragma unroll
                    for (int h2 = 0; h2 < 2; h2++)
                        mma_bf16(acc[mt][g * 2 + h2], fA[mt], fB[g] + h2 * 2);
        }
    }

    const int gq = lane >> 2, tq = lane & 3;
    #pragma unroll
    for (int mt = 0; mt < 4; mt++) {
        const int r0 = bm + warp_m * 64 + mt * 16 + gq;
        #pragma unroll
        for (int nt = 0; nt < 4; nt++) {
            const int col = bn + warp_n * 32 + nt * 8 + tq * 2;
            const float2 bv = *(const float2*)&bias[col];
            float2 v0 = make_float2(acc[mt][nt][0] + bv.x, acc[mt][nt][1] + bv.y);
            float2 v1 = make_float2(acc[mt][nt][2] + bv.x, acc[mt][nt][3] + bv.y);
            *(float2*)&C[(size_t)r0 * ldc + col] = v0;
            *(float2*)&C[(size_t)(r0 + 8) * ldc + col] = v1;
        }
    }
}

// ---------------------------------------------------------------------------
// merged prep
// ---------------------------------------------------------------------------
#define PREP_B1 ((NABC/32)*(DM/32))          // 2880
#define PREP_B2 ((DM/32)*(DM/32))            // 576
#define PREP_B3 (ROWS * DM / 4 / 256)        // 1536
#define PREP_GRID (PREP_B1 + PREP_B2 + PREP_B3)

__device__ __forceinline__ void transpose_tile(
    const float* __restrict__ W, __nv_bfloat16* __restrict__ Th,
    __nv_bfloat16* __restrict__ Tl, int K, int N, int bx, int by, int tid,
    float (*t)[33])
{
    const int n0 = bx * 32, k0 = by * 32;
    const int tx = tid & 31, ty = tid >> 5;
    for (int r = ty; r < 32; r += 8)
        t[r][tx] = W[(size_t)(k0 + r) * N + n0 + tx];
    __syncthreads();
    for (int r = ty; r < 32; r += 8) {
        const float v = t[tx][r];
        const __nv_bfloat16 h = __float2bfloat16(v);
        const __nv_bfloat16 l = __float2bfloat16(v - __bfloat162float(h));
        Th[(size_t)(n0 + r) * K + k0 + tx] = h;
        Tl[(size_t)(n0 + r) * K + k0 + tx] = l;
    }
}

__global__ void __launch_bounds__(256) prep_kernel(
    const float* __restrict__ Wab, const float* __restrict__ WO,
    const float* __restrict__ x,
    __nv_bfloat16* __restrict__ wth, __nv_bfloat16* __restrict__ wtl,
    __nv_bfloat16* __restrict__ woth, __nv_bfloat16* __restrict__ wotl,
    __nv_bfloat16* __restrict__ xh, __nv_bfloat16* __restrict__ xl)
{
    __shared__ float t[32][33];
    int bid = blockIdx.x;
    const int tid = threadIdx.x;
    if (bid < PREP_B1) {
        transpose_tile(Wab, wth, wtl, DM, NABC, bid % (NABC/32), bid / (NABC/32),
                       tid, t);
    } else if (bid < PREP_B1 + PREP_B2) {
        bid -= PREP_B1;
        transpose_tile(WO, woth, wotl, DM, DM, bid % (DM/32), bid / (DM/32),
                       tid, t);
    } else {
        bid -= PREP_B1 + PREP_B2;
        const int i = bid * 256 + tid;
        float4 v = ((const float4*)x)[i];
        uint32_t hx[2], lx[2];
        split4(v, hx, lx);
        ((uint2*)xh)[i] = make_uint2(hx[0], hx[1]);
        ((uint2*)xl)[i] = make_uint2(lx[0], lx[1]);
    }
}

// ---------------------------------------------------------------------------
// Tensor-core local trittention v12: round-14 geometry (proven regs=80,
// occ 34%) + register-neutral ALU cuts:
//  - static mask as one 32-bit bitmask (pk<=pj term)
//  - dynamic mask as single const-vs-reg compare (nt*8+e > kthr-kbase)
//  - fused exp constant: ex2(v * log2e/64)  (1 FMUL + MUFU per element)
// ---------------------------------------------------------------------------
#define FOFF3 (240 * STR + 32)
#define ATTN_SMEM (FOFF3 * 4 + 64 * BRS)     // 74624 B
#define EXC 0.02254170249359f                // log2(e)/64

__global__ void __launch_bounds__(256, 3) attn_kernel(
    const float* __restrict__ abcde,
    __nv_bfloat16* __restrict__ zh, __nv_bfloat16* __restrict__ zl)
{
    extern __shared__ float sm[];
    float* sc  = sm;
    float* sa  = sc  + 16 * STR;
    float* sd  = sa  + 64 * STR;
    float* se  = sd  + 64 * STR;
    float* SjM = se  + 64 * STR;
    float* SkM = SjM + 16 * STR;
    float* red = SkM + 16 * STR;

    const uint32_t sbase = smem_u32(sm);
    const uint32_t sbh   = sbase + FOFF3 * 4;

    const int blk  = blockIdx.x;
    const int half = blk & 1;
    const int w    = (blk >> 1) & (NW - 1);
    const int hb   = blk >> 6;
    const int h    = hb % NH;
    const int b    = hb / NH;
    const int tid  = threadIdx.x;
    const int baseRow = b * SEQ + w * WIN;

    {
        const int i = tid >> 4, dq = (tid & 15) << 2;
        float4 v = *(const float4*)&abcde[
            (size_t)(baseRow + half * 16 + i) * NABC + (2 * NH + h) * DH + dq];
        *(float4*)&sc[i * STR + dq] = v;
    }
    for (int p = tid; p < 64 * 16; p += 256) {
        const int jj = p >> 4, dq = (p & 15) << 2;
        float4 z4 = make_float4(0.f, 0.f, 0.f, 0.f);
        float4 va = z4, vb = z4, vd = z4, ve = z4;
        if (w > 0 || jj >= 32) {
            const size_t r = (size_t)(baseRow - 32 + jj) * NABC;
            va = *(const float4*)&abcde[r + (0 * NH + h) * DH + dq];
            vb = *(const float4*)&abcde[r + (1 * NH + h) * DH + dq];
            vd = *(const float4*)&abcde[r + (3 * NH + h) * DH + dq];
            ve = *(const float4*)&abcde[r + (4 * NH + h) * DH + dq];
        }
        *(float4*)&sa[jj * STR + dq] = va;
        *(float4*)&sd[jj * STR + dq] = vd;
        *(float4*)&se[jj * STR + dq] = ve;
        sts64(sbh + jj * BRS + dq * 2,
              pack_bf16x2(vb.x, vb.y), pack_bf16x2(vb.z, vb.w));
    }
    for (int p = tid; p < 32 * STR; p += 256) SjM[p] = 0.f;
    __syncthreads();

    const int wid = tid >> 5, lane = tid & 31;
    const int wj = wid >> 1, wk = wid & 1;
    const int lr = lane & 7, part = lane >> 3;
    const int gq = lane >> 2, tq = lane & 3;

    const uint32_t b_frag_base =
        (uint32_t)((32 * wk + lr + (part >> 1) * 8) * BRS + (part & 1) * 16);

    const int isel = wj >> 1;
    const int jb   = 32 * (wj & 1);
    const int kbase = 32 * wk + tq * 2;        // k = kbase + nt*8 + e

    // static mask bitmask: bit (mt<<4)|(nt<<2)|rg  <=>  pk <= pj
    uint32_t mstat = 0;
    #pragma unroll
    for (int mt = 0; mt < 2; mt++)
        #pragma unroll
        for (int nt = 0; nt < 4; nt++)
            #pragma unroll
            for (int rg = 0; rg < 4; rg++) {
                const int e = rg & 1, jsel = rg >> 1;
                const int k = kbase + nt * 8 + e;
                const int j = jb + 16 * mt + gq + jsel * 8;
                const int pk = (w == 0 && k < 32) ? 0 : (w * WIN - WIN + k);
                const int pj = (w == 0 && j < 32) ? 0 : (w * WIN - WIN + j);
                if (pk <= pj) mstat |= 1u << ((mt << 4) | (nt << 2) | rg);
            }

    for (int t = 0; t < 8; t++) {
        const int ilw = t * 2 + isel;
        // dynamic mask: qi < pk  <=>  kbase + nt*8 + e > 32 + half*16 + ilw
        const int kd = 32 + half * 16 + ilw - kbase;   // mask if nt*8+e > kd

        float acc[2][4][4] = {};
        #pragma unroll
        for (int s = 0; s < 4; s++) {
            const int kc = s * 16 + tq * 2;
            const float2 cc0 = *(const float2*)&sc[ilw * STR + kc];
            const float2 cc8 = *(const float2*)&sc[ilw * STR + kc + 8];
            uint32_t fA[2][4];
            #pragma unroll
            for (int mt = 0; mt < 2; mt++) {
                const int j0 = jb + 16 * mt + gq;
                const float2 aA = *(const float2*)&sa[j0 * STR + kc];
                const float2 aB = *(const float2*)&sa[(j0 + 8) * STR + kc];
                const float2 aC = *(const float2*)&sa[j0 * STR + kc + 8];
                const float2 aD = *(const float2*)&sa[(j0 + 8) * STR + kc + 8];
                fA[mt][0] = pack_bf16x2(aA.x * cc0.x, aA.y * cc0.y);
                fA[mt][1] = pack_bf16x2(aB.x * cc0.x, aB.y * cc0.y);
                fA[mt][2] = pack_bf16x2(aC.x * cc8.x, aC.y * cc8.y);
                fA[mt][3] = pack_bf16x2(aD.x * cc8.x, aD.y * cc8.y);
            }
            uint32_t fB[2][4];
            #pragma unroll
            for (int g = 0; g < 2; g++)
                ldm_x4(fB[g], sbh + b_frag_base + g * 16 * BRS + s * 32);

            #pragma unroll
            for (int mt = 0; mt < 2; mt++)
                #pragma unroll
                for (int g = 0; g < 2; g++)
                    #pragma unroll
                    for (int h2 = 0; h2 < 2; h2++)
                        mma_bf16(acc[mt][g * 2 + h2], fA[mt], fB[g] + h2 * 2);
        }

        // mask + fused exp
        #pragma unroll
        for (int mt = 0; mt < 2; mt++)
            #pragma unroll
            for (int nt = 0; nt < 4; nt++)
                #pragma unroll
                for (int rg = 0; rg < 4; rg++) {
                    const float v = acc[mt][nt][rg];
                    const bool m = (nt * 8 + (rg & 1) > kd)
                                 | ((mstat >> ((mt << 4) | (nt << 2) | rg)) & 1u)
                                 | (v == 0.0f);
                    acc[mt][nt][rg] = m ? 0.0f : ex2f(v * EXC);
                }

        // Sj (sum over k): quad shuffles + atomics
        #pragma unroll
        for (int mt = 0; mt < 2; mt++) {
            float s0 = 0.f, s1 = 0.f;
            #pragma unroll
            for (int nt = 0; nt < 4; nt++) {
                s0 += acc[mt][nt][0] + acc[mt][nt][1];
                s1 += acc[mt][nt][2] + acc[mt][nt][3];
            }
            s0 += __shfl_xor_sync(0xffffffffu, s0, 1);
            s1 += __shfl_xor_sync(0xffffffffu, s1, 1);
            s0 += __shfl_xor_sync(0xffffffffu, s0, 2);
            s1 += __shfl_xor_sync(0xffffffffu, s1, 2);
            if (tq == 0) {
                const int ja = jb + 16 * mt + gq;
                atomicAdd(&SjM[ilw * STR + ja], s0);
                atomicAdd(&SjM[ilw * STR + ja + 8], s1);
            }
        }
        // Sk (sum over j): xor 4/8/16 shuffles + atomics
        {
            float t0[4], t1[4];
            #pragma unroll
            for (int nt = 0; nt < 4; nt++) {
                t0[nt] = acc[0][nt][0] + acc[0][nt][2]
                       + acc[1][nt][0] + acc[1][nt][2];
                t1[nt] = acc[0][nt][1] + acc[0][nt][3]
                       + acc[1][nt][1] + acc[1][nt][3];
            }
            #pragma unroll
            for (int o = 4; o <= 16; o <<= 1)
                #pragma unroll
                for (int nt = 0; nt < 4; nt++) {
                    t0[nt] += __shfl_xor_sync(0xffffffffu, t0[nt], o);
                    t1[nt] += __shfl_xor_sync(0xffffffffu, t1[nt], o);
                }
            if (gq == 0) {
                #pragma unroll
                for (int nt = 0; nt < 4; nt++) {
                    const int k = 32 * wk + nt * 8 + tq * 2;
                    atomicAdd(&SkM[ilw * STR + k],     t0[nt]);
                    atomicAdd(&SkM[ilw * STR + k + 1], t1[nt]);
                }
            }
        }
    }
    __syncthreads();

    if (tid < 16) {
        const float* r = &SjM[tid * STR];
        float s = 0.f;
        #pragma unroll 8
        for (int j = 0; j < 64; j++) s += r[j];
        red[tid] = (s > 0.f) ? (1.0f / s) : -1.0f;
    }
    __syncthreads();

    {
        const int il = tid >> 4;
        const int d0 = (tid & 15) << 2;
        const float invv = red[il];
        const bool  uni  = (invv < 0.f);
        const float uadd = uni ? 1.0f : 0.0f;
        const float fscl = uni ? (1.0f / 64.0f) : invv;
        float z[4] = {};
        #pragma unroll 4
        for (int j = 0; j < 64; j++) {
            const float sj = SjM[il * STR + j] + uadd;
            const float sk = SkM[il * STR + j] + uadd;
            float4 dA = *(const float4*)&sd[j * STR + d0];
            float4 eA = *(const float4*)&se[j * STR + d0];
            z[0] = fmaf(sj, dA.x, z[0]); z[1] = fmaf(sj, dA.y, z[1]);
            z[2] = fmaf(sj, dA.z, z[2]); z[3] = fmaf(sj, dA.w, z[3]);
            z[0] = fmaf(sk, eA.x, z[0]); z[1] = fmaf(sk, eA.y, z[1]);
            z[2] = fmaf(sk, eA.z, z[2]); z[3] = fmaf(sk, eA.w, z[3]);
        }
        uint32_t uh[2], ul[2];
        #pragma unroll
        for (int q = 0; q < 2; q++) {
            const float f0 = z[2 * q] * fscl, f1 = z[2 * q + 1] * fscl;
            __nv_bfloat16 h0 = __float2bfloat16(f0);
            __nv_bfloat16 h1 = __float2bfloat16(f1);
            __nv_bfloat16 l0 = __float2bfloat16(f0 - __bfloat162float(h0));
            __nv_bfloat16 l1 = __float2bfloat16(f1 - __bfloat162float(h1));
            uh[q] = (uint32_t)__bfloat16_as_ushort(h0)
                  | ((uint32_t)__bfloat16_as_ushort(h1) << 16);
            ul[q] = (uint32_t)__bfloat16_as_ushort(l0)
                  | ((uint32_t)__bfloat16_as_ushort(l1) << 16);
        }
        const size_t off =
            (size_t)(baseRow + half * 16 + il) * DM + h * DH + d0;
        *(uint2*)(zh + off) = make_uint2(uh[0], uh[1]);
        *(uint2*)(zl + off) = make_uint2(ul[0], ul[1]);
    }
}

// ---------------------------------------------------------------------------
extern "C" void kernel_launch(void* const* d_in, const int* in_sizes, int n_in,
                              void* d_out, int out_size)
{
    const float* x   = (const float*)d_in[0];
    const float* Wab = (const float*)d_in[1];
    const float* bab = (const float*)d_in[2];
    const float* WO  = (const float*)d_in[3];
    const float* bO  = (const float*)d_in[4];
    float* out = (float*)d_out;

    float* abcde_p = nullptr;
    __nv_bfloat16 *xh, *xl, *wth, *wtl, *woth, *wotl, *zh, *zl;
    cudaGetSymbolAddress((void**)&abcde_p, g_abcde);
    cudaGetSymbolAddress((void**)&xh,   g_xh);
    cudaGetSymbolAddress((void**)&xl,   g_xl);
    cudaGetSymbolAddress((void**)&wth,  g_wth);
    cudaGetSymbolAddress((void**)&wtl,  g_wtl);
    cudaGetSymbolAddress((void**)&woth, g_woth);
    cudaGetSymbolAddress((void**)&wotl, g_wotl);
    cudaGetSymbolAddress((void**)&zh,   g_zh);
    cudaGetSymbolAddress((void**)&zl,   g_zl);

    cudaFuncSetAttribute(tc_gemm_kernel,
                         cudaFuncAttributeMaxDynamicSharedMemorySize, GEMM_SMEM);
    cudaFuncSetAttribute(tc_gemm1_kernel,
                         cudaFuncAttributeMaxDynamicSharedMemorySize, GEMM1_SMEM);
    cudaFuncSetAttribute(attn_kernel,
                         cudaFuncAttributeMaxDynamicSharedMemorySize, ATTN_SMEM);

    prep_kernel<<<PREP_GRID, 256>>>(Wab, WO, x, wth, wtl, woth, wotl, xh, xl);

    tc_gemm1_kernel<<<dim3(NABC_ABC / 128, ROWS / 128), 256, GEMM1_SMEM>>>(
        xh, wth, bab, abcde_p, NABC, DM);

    tc_gemm_kernel<<<dim3(NABC_DE / 128, ROWS / 128), 256, GEMM_SMEM>>>(
        xh, xl, wth + (size_t)NABC_ABC * DM, wtl + (size_t)NABC_ABC * DM,
        bab + NABC_ABC, abcde_p + NABC_ABC, NABC, DM);

    attn_kernel<<<BSZ * NH * NW * 2, 256, ATTN_SMEM>>>(abcde_p, zh, zl);

    tc_gemm_kernel<<<dim3(DM / 128, ROWS / 128), 256, GEMM_SMEM>>>(
        zh, zl, woth, wotl, bO, out, DM, DM);
}